// round 1
// baseline (speedup 1.0000x reference)
#include <cuda_runtime.h>
#include <cuda_bf16.h>
#include <cstddef>

// Problem constants
#define BATCH   2
#define SEQLEN  1024
#define DMODEL  2048
#define DINNER  4096
#define DSTATE  16
#define DTRANK  128
#define DCONV   4
#define MROWS   (BATCH * SEQLEN)          // 2048
#define XDBLW   (DTRANK + 2 * DSTATE)     // 160

// ---------------- scratch (no allocations allowed) ----------------
__device__ float g_xz[(size_t)MROWS * 2 * DINNER];   // in_proj output (x|z)
__device__ float g_xc[(size_t)MROWS * DINNER];       // conv+silu output
__device__ float g_xdbl[(size_t)MROWS * XDBLW];      // x_proj output (dt|B|C)
__device__ float g_delta[(size_t)MROWS * DINNER];    // softplus(dt_proj + b)
__device__ float g_y[(size_t)MROWS * DINNER];        // scan output (gated)

// ---------------- helpers ----------------
__device__ __forceinline__ float softplusf(float x) {
    return x > 20.f ? x : log1pf(__expf(x));
}
__device__ __forceinline__ float siluf(float x) {
    return x / (1.f + __expf(-x));
}

// ---------------- generic NT SGEMM ----------------
// C[m][n] = sum_k A[m][k] * W[n][k]
// A: M x K row-major with row stride lda ; W: N x K row-major (stride K)
// C: M x N row-major (stride N)
// EPI: 0 = none ; 1 = softplus(val + bias[n])
#define BM 128
#define BN 128
#define BKK 16
#define TM 8
#define TN 8

template <int EPI>
__global__ void __launch_bounds__(256)
sgemm_nt(const float* __restrict__ A, int lda,
         const float* __restrict__ W,
         const float* __restrict__ bias,
         float* __restrict__ C,
         int M, int N, int K)
{
    __shared__ float As[BKK][BM];
    __shared__ float Ws[BKK][BN];

    const int tid = threadIdx.x;
    const int bm = blockIdx.y * BM;
    const int bn = blockIdx.x * BN;
    const int tx = tid % (BN / TN);   // 0..15
    const int ty = tid / (BN / TN);   // 0..15

    const int lrow  = tid >> 2;        // 0..63
    const int lcol4 = (tid & 3) << 2;  // 0,4,8,12

    float acc[TM][TN];
    #pragma unroll
    for (int i = 0; i < TM; i++)
        #pragma unroll
        for (int j = 0; j < TN; j++) acc[i][j] = 0.f;

    for (int k0 = 0; k0 < K; k0 += BKK) {
        // load A tile (always in-bounds: M % BM == 0, K % BKK == 0)
        #pragma unroll
        for (int r = 0; r < BM; r += 64) {
            float4 v = *(const float4*)(A + (size_t)(bm + lrow + r) * lda + k0 + lcol4);
            As[lcol4 + 0][lrow + r] = v.x;
            As[lcol4 + 1][lrow + r] = v.y;
            As[lcol4 + 2][lrow + r] = v.z;
            As[lcol4 + 3][lrow + r] = v.w;
        }
        // load W tile (guard N: x_proj has N=160)
        #pragma unroll
        for (int r = 0; r < BN; r += 64) {
            int wrow = bn + lrow + r;
            float4 v = make_float4(0.f, 0.f, 0.f, 0.f);
            if (wrow < N)
                v = *(const float4*)(W + (size_t)wrow * K + k0 + lcol4);
            Ws[lcol4 + 0][lrow + r] = v.x;
            Ws[lcol4 + 1][lrow + r] = v.y;
            Ws[lcol4 + 2][lrow + r] = v.z;
            Ws[lcol4 + 3][lrow + r] = v.w;
        }
        __syncthreads();

        #pragma unroll
        for (int k = 0; k < BKK; k++) {
            float am[TM], wn[TN];
            #pragma unroll
            for (int i = 0; i < TM; i++) am[i] = As[k][ty * TM + i];
            #pragma unroll
            for (int j = 0; j < TN; j++) wn[j] = Ws[k][tx * TN + j];
            #pragma unroll
            for (int i = 0; i < TM; i++)
                #pragma unroll
                for (int j = 0; j < TN; j++)
                    acc[i][j] = fmaf(am[i], wn[j], acc[i][j]);
        }
        __syncthreads();
    }

    #pragma unroll
    for (int i = 0; i < TM; i++) {
        int m = bm + ty * TM + i;
        #pragma unroll
        for (int j = 0; j < TN; j++) {
            int n = bn + tx * TN + j;
            if (n < N) {
                float v = acc[i][j];
                if (EPI == 1) v = softplusf(v + bias[n]);
                C[(size_t)m * N + n] = v;
            }
        }
    }
}

// ---------------- causal depthwise conv (K=4) + SiLU ----------------
__global__ void conv_silu_kernel(const float* __restrict__ xz,
                                 const float* __restrict__ cw,
                                 const float* __restrict__ cb,
                                 float* __restrict__ xc)
{
    int idx = blockIdx.x * blockDim.x + threadIdx.x;   // over B*L*DINNER
    int d  = idx & (DINNER - 1);
    int bl = idx / DINNER;                              // b*L + l
    int l  = bl & (SEQLEN - 1);

    float acc = cb[d];
    #pragma unroll
    for (int k = 0; k < DCONV; k++) {
        int li = l + k - (DCONV - 1);
        if (li >= 0) {
            float xv = xz[((size_t)(bl + (li - l))) * 2 * DINNER + d];
            acc = fmaf(xv, cw[d * DCONV + k], acc);
        }
    }
    xc[idx] = siluf(acc);
}

// ---------------- selective scan ----------------
// one thread per channel d, 16 states in registers, serial over L
#define SCAN_CH 64   // timesteps of B/C staged per shared-memory chunk
__global__ void __launch_bounds__(128)
scan_kernel(const float* __restrict__ delta,
            const float* __restrict__ xc,
            const float* __restrict__ xdbl,
            const float* __restrict__ xz,
            const float* __restrict__ A,
            const float* __restrict__ Dp,
            float* __restrict__ y)
{
    const int d = blockIdx.x * 128 + threadIdx.x;
    const int b = blockIdx.y;

    float st[DSTATE], a[DSTATE];
    #pragma unroll
    for (int n = 0; n < DSTATE; n++) {
        st[n] = 0.f;
        a[n]  = A[(size_t)d * DSTATE + n];
    }
    const float Dd = Dp[d];

    __shared__ float sB[SCAN_CH][DSTATE];
    __shared__ float sC[SCAN_CH][DSTATE];

    for (int t0 = 0; t0 < SEQLEN; t0 += SCAN_CH) {
        __syncthreads();
        for (int i = threadIdx.x; i < SCAN_CH * 2 * DSTATE; i += 128) {
            int tt = i >> 5;
            int c  = i & 31;
            float v = xdbl[((size_t)(b * SEQLEN + t0 + tt)) * XDBLW + DTRANK + c];
            if (c < DSTATE) sB[tt][c] = v;
            else            sC[tt][c - DSTATE] = v;
        }
        __syncthreads();

        for (int tt = 0; tt < SCAN_CH; tt++) {
            const size_t row  = (size_t)(b * SEQLEN + t0 + tt);
            const size_t base = row * DINNER + d;
            float dlt = delta[base];
            float xv  = xc[base];
            float zv  = xz[row * 2 * DINNER + DINNER + d];
            float dx  = dlt * xv;
            float yv  = 0.f;
            #pragma unroll
            for (int n = 0; n < DSTATE; n++) {
                float e = __expf(dlt * a[n]);
                st[n] = fmaf(e, st[n], dx * sB[tt][n]);
                yv    = fmaf(st[n], sC[tt][n], yv);
            }
            y[base] = (yv + xv * Dd) * siluf(zv);
        }
    }
}

// ---------------- launch ----------------
extern "C" void kernel_launch(void* const* d_in, const int* in_sizes, int n_in,
                              void* d_out, int out_size)
{
    const float* hidden     = (const float*)d_in[0];
    const float* in_proj_w  = (const float*)d_in[1];
    const float* conv_w     = (const float*)d_in[2];
    const float* conv_b     = (const float*)d_in[3];
    const float* x_proj_w   = (const float*)d_in[4];
    const float* dt_proj_w  = (const float*)d_in[5];
    const float* dt_proj_b  = (const float*)d_in[6];
    const float* out_proj_w = (const float*)d_in[7];
    const float* A_in       = (const float*)d_in[8];
    const float* D_param    = (const float*)d_in[9];
    float* out = (float*)d_out;

    static float *p_xz = nullptr, *p_xc = nullptr, *p_xdbl = nullptr,
                 *p_delta = nullptr, *p_y = nullptr;
    if (!p_xz) {
        cudaGetSymbolAddress((void**)&p_xz,    g_xz);
        cudaGetSymbolAddress((void**)&p_xc,    g_xc);
        cudaGetSymbolAddress((void**)&p_xdbl,  g_xdbl);
        cudaGetSymbolAddress((void**)&p_delta, g_delta);
        cudaGetSymbolAddress((void**)&p_y,     g_y);
    }

    // 1) in_proj: (2048 x 2048) @ (8192 x 2048)^T -> xz (2048 x 8192)
    sgemm_nt<0><<<dim3(2 * DINNER / BN, MROWS / BM), 256>>>(
        hidden, DMODEL, in_proj_w, nullptr, p_xz, MROWS, 2 * DINNER, DMODEL);

    // 2) causal depthwise conv + SiLU -> xc (2048 x 4096)
    conv_silu_kernel<<<(MROWS * DINNER) / 256, 256>>>(p_xz, conv_w, conv_b, p_xc);

    // 3) x_proj: (2048 x 4096) @ (160 x 4096)^T -> x_dbl (2048 x 160)
    sgemm_nt<0><<<dim3((XDBLW + BN - 1) / BN, MROWS / BM), 256>>>(
        p_xc, DINNER, x_proj_w, nullptr, p_xdbl, MROWS, XDBLW, DINNER);

    // 4) dt_proj + bias + softplus: (2048 x 128[stride 160]) @ (4096 x 128)^T -> delta
    sgemm_nt<1><<<dim3(DINNER / BN, MROWS / BM), 256>>>(
        p_xdbl, XDBLW, dt_proj_w, dt_proj_b, p_delta, MROWS, DINNER, DTRANK);

    // 5) selective scan (+ x*D, * silu(z)) -> y (2048 x 4096)
    scan_kernel<<<dim3(DINNER / 128, BATCH), 128>>>(
        p_delta, p_xc, p_xdbl, p_xz, A_in, D_param, p_y);

    // 6) out_proj: (2048 x 4096) @ (2048 x 4096)^T -> out (2048 x 2048)
    sgemm_nt<0><<<dim3(DMODEL / BN, MROWS / BM), 256>>>(
        p_y, DINNER, out_proj_w, nullptr, out, MROWS, DMODEL, DINNER);
}

// round 5
// speedup vs baseline: 2.0617x; 2.0617x over previous
#include <cuda_runtime.h>
#include <cuda_bf16.h>
#include <cstdint>
#include <cstddef>

// NOTE: resubmission of the Round-3 kernel (non-trans ldmatrix for B).
// Round 4 bench failed on infra ("GB300 container failed twice") before
// this fix was ever measured.

// Problem constants
#define BATCH   2
#define SEQLEN  1024
#define DMODEL  2048
#define DINNER  4096
#define DSTATE  16
#define DTRANK  128
#define DCONV   4
#define MROWS   (BATCH * SEQLEN)          // 2048
#define XDBLW   (DTRANK + 2 * DSTATE)     // 160

// ---------------- scratch (no allocations allowed) ----------------
__device__ float g_xz[(size_t)MROWS * 2 * DINNER];   // in_proj output (x|z)
__device__ float g_xc[(size_t)MROWS * DINNER];       // conv+silu output
__device__ float g_xdbl[(size_t)MROWS * XDBLW];      // x_proj output (dt|B|C)
__device__ float g_delta[(size_t)MROWS * DINNER];    // softplus(dt_proj + b)
__device__ float g_y[(size_t)MROWS * DINNER];        // scan output (gated)

// ---------------- helpers ----------------
__device__ __forceinline__ uint32_t smem_u32(const void* p) {
    uint32_t a;
    asm("{ .reg .u64 t; cvta.to.shared.u64 t, %1; cvt.u32.u64 %0, t; }" : "=r"(a) : "l"(p));
    return a;
}
__device__ __forceinline__ uint32_t swz128(uint32_t off) {
    return off ^ ((off >> 3) & 0x70);
}
__device__ __forceinline__ float softplusf(float x) {
    return x > 20.f ? x : log1pf(__expf(x));
}
__device__ __forceinline__ float siluf(float x) {
    return x / (1.f + __expf(-x));
}
// pack truncated-bf16 of two floats (low half = hi16(x), high half = hi16(y))
__device__ __forceinline__ uint32_t pack_hi_trunc(float x, float y) {
    return __byte_perm(__float_as_uint(x), __float_as_uint(y), 0x7632);
}
__device__ __forceinline__ uint32_t pack_bf16x2(float lo_val, float hi_val) {
    uint32_t r;
    asm("cvt.rn.bf16x2.f32 %0, %1, %2;" : "=r"(r) : "f"(hi_val), "f"(lo_val));
    return r;
}
__device__ __forceinline__ float trunc_bf16_val(float x) {
    return __uint_as_float(__float_as_uint(x) & 0xFFFF0000u);
}

__device__ __forceinline__ void ldsm4(uint32_t (&r)[4], uint32_t addr) {
    asm volatile("ldmatrix.sync.aligned.m8n8.x4.shared.b16 {%0,%1,%2,%3}, [%4];"
                 : "=r"(r[0]), "=r"(r[1]), "=r"(r[2]), "=r"(r[3]) : "r"(addr));
}
__device__ __forceinline__ void mma16816(float (&c)[4], const uint32_t (&a)[4],
                                         uint32_t b0, uint32_t b1) {
    asm volatile(
        "mma.sync.aligned.m16n8k16.row.col.f32.bf16.bf16.f32 "
        "{%0,%1,%2,%3}, {%4,%5,%6,%7}, {%8,%9}, {%0,%1,%2,%3};"
        : "+f"(c[0]), "+f"(c[1]), "+f"(c[2]), "+f"(c[3])
        : "r"(a[0]), "r"(a[1]), "r"(a[2]), "r"(a[3]), "r"(b0), "r"(b1));
}

// ---------------- bf16x2-split MMA GEMM: C[m][n] = sum_k A[m][k] * W[n][k] ----------------
// A: M x K row-major (stride lda), W: N x K row-major (stride K), C: M x N row-major.
// EPI: 0 = none ; 1 = softplus(v + bias[n])
#define BM 128
#define BN 128
#define KC 32                     // fp32 K elements per chunk
#define SM_A 0
#define SM_B 16384
#define STAGE_BYTES 32768         // A tile 16KB (hi|lo in 128B rows) + B tile 16KB
#define GEMM_SMEM (2 * STAGE_BYTES)

template <int EPI>
__global__ void __launch_bounds__(256, 1)
gemm_mma(const float* __restrict__ A, int lda,
         const float* __restrict__ W,
         const float* __restrict__ bias,
         float* __restrict__ C,
         int M, int N, int K)
{
    extern __shared__ __align__(1024) char smem[];
    const uint32_t sbase = smem_u32(smem);
    const int tid = threadIdx.x;
    const int lid = tid & 31;
    const int wid = tid >> 5;
    const int wm = wid & 1;        // 0..1 (64-row band)
    const int wn = wid >> 1;       // 0..3 (32-col band)
    const int bm = blockIdx.y * BM;
    const int bn = blockIdx.x * BN;

    float acc[4][4][4];
    #pragma unroll
    for (int i = 0; i < 4; i++)
        #pragma unroll
        for (int j = 0; j < 4; j++)
            #pragma unroll
            for (int q = 0; q < 4; q++) acc[i][j][q] = 0.f;

    const int nch = K / KC;
    const int lr0 = tid >> 3;      // 0..31 (+u*32 -> 128 rows)
    const int lc4 = tid & 7;       // float4 column 0..7

    float4 va[4], vb[4];

    // ---- loaders / converter ----
    auto ldA = [&](int k0) {
        #pragma unroll
        for (int u = 0; u < 4; u++)
            va[u] = *(const float4*)(A + (size_t)(bm + lr0 + u * 32) * lda + k0 + lc4 * 4);
    };
    auto ldB = [&](int k0) {
        #pragma unroll
        for (int u = 0; u < 4; u++) {
            int r = bn + lr0 + u * 32;
            vb[u] = (r < N) ? *(const float4*)(W + (size_t)r * K + k0 + lc4 * 4)
                            : make_float4(0.f, 0.f, 0.f, 0.f);
        }
    };
    auto stq = [&](int buf) {
        char* s = smem + buf * STAGE_BYTES;
        #pragma unroll
        for (int u = 0; u < 4; u++) {
            uint32_t off = swz128((uint32_t)((lr0 + u * 32) * 128 + lc4 * 8));
            float4 v = va[u];
            float hx = trunc_bf16_val(v.x), hy = trunc_bf16_val(v.y);
            float hz = trunc_bf16_val(v.z), hw = trunc_bf16_val(v.w);
            *(uint2*)(s + SM_A + off) =
                make_uint2(pack_hi_trunc(v.x, v.y), pack_hi_trunc(v.z, v.w));
            *(uint2*)(s + SM_A + (off ^ 64)) =
                make_uint2(pack_bf16x2(v.x - hx, v.y - hy), pack_bf16x2(v.z - hz, v.w - hw));
            v = vb[u];
            hx = trunc_bf16_val(v.x); hy = trunc_bf16_val(v.y);
            hz = trunc_bf16_val(v.z); hw = trunc_bf16_val(v.w);
            *(uint2*)(s + SM_B + off) =
                make_uint2(pack_hi_trunc(v.x, v.y), pack_hi_trunc(v.z, v.w));
            *(uint2*)(s + SM_B + (off ^ 64)) =
                make_uint2(pack_bf16x2(v.x - hx, v.y - hy), pack_bf16x2(v.z - hz, v.w - hw));
        }
    };

    // ---- prologue ----
    ldA(0); ldB(0); stq(0);
    __syncthreads();

    const int lrow = lid & 15;
    const int lch  = lid >> 4;

    for (int ch = 0; ch < nch; ch++) {
        if (ch + 1 < nch) { ldA((ch + 1) * KC); ldB((ch + 1) * KC); }

        // ---- compute chunk from buf (ch&1): 2 k16 steps, 3-term split ----
        const uint32_t sA = sbase + (ch & 1) * STAGE_BYTES + SM_A;
        const uint32_t sB = sbase + (ch & 1) * STAGE_BYTES + SM_B;
        #pragma unroll
        for (int s = 0; s < 2; s++) {
            uint32_t ah[4][4], al[4][4];
            #pragma unroll
            for (int mt = 0; mt < 4; mt++) {
                uint32_t off = (uint32_t)((wm * 64 + mt * 16 + lrow) * 128 + s * 32 + lch * 16);
                ldsm4(ah[mt], sA + swz128(off));
                ldsm4(al[mt], sA + swz128(off ^ 64));
            }
            // B tiles: W is N x K (k contiguous) == exactly the col-major k x n
            // fragment layout -> NON-trans ldmatrix (this was the R3 bug)
            uint32_t bh[2][4], bl[2][4];
            #pragma unroll
            for (int p = 0; p < 2; p++) {
                uint32_t off = (uint32_t)((wn * 32 + p * 16 + lrow) * 128 + s * 32 + lch * 16);
                ldsm4(bh[p], sB + swz128(off));
                ldsm4(bl[p], sB + swz128(off ^ 64));
            }
            #pragma unroll
            for (int mt = 0; mt < 4; mt++)
                #pragma unroll
                for (int nt = 0; nt < 4; nt++) {
                    const int p = nt >> 1, q = nt & 1;
                    mma16816(acc[mt][nt], ah[mt], bh[p][q], bh[p][q + 2]);
                    mma16816(acc[mt][nt], ah[mt], bl[p][q], bl[p][q + 2]);
                    mma16816(acc[mt][nt], al[mt], bh[p][q], bh[p][q + 2]);
                }
        }

        if (ch + 1 < nch) { stq((ch + 1) & 1); __syncthreads(); }
    }

    // ---- epilogue: c0,c1 -> (row, col..col+1); c2,c3 -> (row+8, ...) ----
    #pragma unroll
    for (int mt = 0; mt < 4; mt++) {
        const int m = bm + wm * 64 + mt * 16 + (lid >> 2);
        #pragma unroll
        for (int nt = 0; nt < 4; nt++) {
            const int n = bn + wn * 32 + nt * 8 + (lid & 3) * 2;
            if (n < N) {
                float v0 = acc[mt][nt][0], v1 = acc[mt][nt][1];
                float v2 = acc[mt][nt][2], v3 = acc[mt][nt][3];
                if (EPI == 1) {
                    v0 = softplusf(v0 + bias[n]);     v1 = softplusf(v1 + bias[n + 1]);
                    v2 = softplusf(v2 + bias[n]);     v3 = softplusf(v3 + bias[n + 1]);
                }
                *(float2*)(C + (size_t)m * N + n)       = make_float2(v0, v1);
                *(float2*)(C + (size_t)(m + 8) * N + n) = make_float2(v2, v3);
            }
        }
    }
}

// ---------------- causal depthwise conv (K=4) + SiLU ----------------
__global__ void conv_silu_kernel(const float* __restrict__ xz,
                                 const float* __restrict__ cw,
                                 const float* __restrict__ cb,
                                 float* __restrict__ xc)
{
    int idx = blockIdx.x * blockDim.x + threadIdx.x;
    int d  = idx & (DINNER - 1);
    int bl = idx / DINNER;
    int l  = bl & (SEQLEN - 1);

    float acc = cb[d];
    #pragma unroll
    for (int k = 0; k < DCONV; k++) {
        int li = l + k - (DCONV - 1);
        if (li >= 0) {
            float xv = xz[((size_t)(bl + (li - l))) * 2 * DINNER + d];
            acc = fmaf(xv, cw[d * DCONV + k], acc);
        }
    }
    xc[idx] = siluf(acc);
}

// ---------------- selective scan ----------------
#define SCAN_CH 64
__global__ void __launch_bounds__(64)
scan_kernel(const float* __restrict__ delta,
            const float* __restrict__ xc,
            const float* __restrict__ xdbl,
            const float* __restrict__ xz,
            const float* __restrict__ A,
            const float* __restrict__ Dp,
            float* __restrict__ y)
{
    const int d = blockIdx.x * 64 + threadIdx.x;
    const int b = blockIdx.y;

    float st[DSTATE], a[DSTATE];
    #pragma unroll
    for (int n = 0; n < DSTATE; n++) {
        st[n] = 0.f;
        a[n]  = A[(size_t)d * DSTATE + n];
    }
    const float Dd = Dp[d];
    const float a0 = a[0];
    bool fast = true;
    #pragma unroll
    for (int n = 0; n < DSTATE; n++) fast = fast && (a[n] == a0 * (n + 1));

    __shared__ float sB[SCAN_CH][DSTATE];
    __shared__ float sC[SCAN_CH][DSTATE];

    for (int t0 = 0; t0 < SEQLEN; t0 += SCAN_CH) {
        __syncthreads();
        for (int i = threadIdx.x; i < SCAN_CH * 2 * DSTATE; i += 64) {
            int tt = i >> 5;
            int c  = i & 31;
            float v = xdbl[((size_t)(b * SEQLEN + t0 + tt)) * XDBLW + DTRANK + c];
            if (c < DSTATE) sB[tt][c] = v;
            else            sC[tt][c - DSTATE] = v;
        }
        __syncthreads();

        for (int tt = 0; tt < SCAN_CH; tt++) {
            const size_t row  = (size_t)(b * SEQLEN + t0 + tt);
            const size_t base = row * DINNER + d;
            float dlt = delta[base];
            float xv  = xc[base];
            float zv  = xz[row * 2 * DINNER + DINNER + d];
            float dx  = dlt * xv;
            float e[DSTATE];
            if (fast) {
                float p  = __expf(dlt * a0);
                float p2 = p * p, p3 = p2 * p, p4 = p2 * p2, p8 = p4 * p4;
                e[0] = p;       e[1] = p2;      e[2] = p3;      e[3] = p4;
                e[4] = p4 * p;  e[5] = p4 * p2; e[6] = p4 * p3; e[7] = p8;
                e[8] = p8 * p;  e[9] = p8 * p2; e[10] = p8 * p3; e[11] = p8 * p4;
                e[12] = e[8] * p4; e[13] = e[9] * p4; e[14] = e[10] * p4; e[15] = p8 * p8;
            } else {
                #pragma unroll
                for (int n = 0; n < DSTATE; n++) e[n] = __expf(dlt * a[n]);
            }
            float yv = 0.f;
            #pragma unroll
            for (int n = 0; n < DSTATE; n++) {
                st[n] = fmaf(e[n], st[n], dx * sB[tt][n]);
                yv    = fmaf(st[n], sC[tt][n], yv);
            }
            y[base] = (yv + xv * Dd) * siluf(zv);
        }
    }
}

// ---------------- launch ----------------
extern "C" void kernel_launch(void* const* d_in, const int* in_sizes, int n_in,
                              void* d_out, int out_size)
{
    const float* hidden     = (const float*)d_in[0];
    const float* in_proj_w  = (const float*)d_in[1];
    const float* conv_w     = (const float*)d_in[2];
    const float* conv_b     = (const float*)d_in[3];
    const float* x_proj_w   = (const float*)d_in[4];
    const float* dt_proj_w  = (const float*)d_in[5];
    const float* dt_proj_b  = (const float*)d_in[6];
    const float* out_proj_w = (const float*)d_in[7];
    const float* A_in       = (const float*)d_in[8];
    const float* D_param    = (const float*)d_in[9];
    float* out = (float*)d_out;

    static float *p_xz = nullptr, *p_xc = nullptr, *p_xdbl = nullptr,
                 *p_delta = nullptr, *p_y = nullptr;
    static bool init_done = false;
    if (!init_done) {
        cudaGetSymbolAddress((void**)&p_xz,    g_xz);
        cudaGetSymbolAddress((void**)&p_xc,    g_xc);
        cudaGetSymbolAddress((void**)&p_xdbl,  g_xdbl);
        cudaGetSymbolAddress((void**)&p_delta, g_delta);
        cudaGetSymbolAddress((void**)&p_y,     g_y);
        cudaFuncSetAttribute(gemm_mma<0>, cudaFuncAttributeMaxDynamicSharedMemorySize, GEMM_SMEM);
        cudaFuncSetAttribute(gemm_mma<1>, cudaFuncAttributeMaxDynamicSharedMemorySize, GEMM_SMEM);
        init_done = true;
    }

    // 1) in_proj: (2048 x 2048) @ (8192 x 2048)^T -> xz
    gemm_mma<0><<<dim3(2 * DINNER / BN, MROWS / BM), 256, GEMM_SMEM>>>(
        hidden, DMODEL, in_proj_w, nullptr, p_xz, MROWS, 2 * DINNER, DMODEL);

    // 2) causal depthwise conv + SiLU
    conv_silu_kernel<<<(MROWS * DINNER) / 256, 256>>>(p_xz, conv_w, conv_b, p_xc);

    // 3) x_proj: (2048 x 4096) @ (160 x 4096)^T -> x_dbl
    gemm_mma<0><<<dim3((XDBLW + BN - 1) / BN, MROWS / BM), 256, GEMM_SMEM>>>(
        p_xc, DINNER, x_proj_w, nullptr, p_xdbl, MROWS, XDBLW, DINNER);

    // 4) dt_proj + bias + softplus: (2048 x 128[stride 160]) @ (4096 x 128)^T -> delta
    gemm_mma<1><<<dim3(DINNER / BN, MROWS / BM), 256, GEMM_SMEM>>>(
        p_xdbl, XDBLW, dt_proj_w, dt_proj_b, p_delta, MROWS, DINNER, DTRANK);

    // 5) selective scan (+ x*D, * silu(z)) -> y
    scan_kernel<<<dim3(DINNER / 64, BATCH), 64>>>(
        p_delta, p_xc, p_xdbl, p_xz, A_in, D_param, p_y);

    // 6) out_proj: (2048 x 4096) @ (2048 x 4096)^T -> out
    gemm_mma<0><<<dim3(DMODEL / BN, MROWS / BM), 256, GEMM_SMEM>>>(
        p_y, DINNER, out_proj_w, nullptr, out, MROWS, DMODEL, DINNER);
}